// round 8
// baseline (speedup 1.0000x reference)
#include <cuda_runtime.h>
#include <math.h>

#define E_EDGES 262144
#define NNODE   2048
#define NREL    4
#define NSEG    8192          /* NNODE*NREL */
#define DDIM    512
#define NHEAD   8
#define DH      64
#define EPSV    1e-10f
#define NSEL    24576         /* NREL*NNODE*3 */
#define GS      36            /* smem stride (floats) for GEMM mma tiles */
#define KS      68            /* smem stride for scores tiles (64 + 4 pad) */
#define NRH     32            /* NREL*NHEAD */

// ---------------- device scratch (static; no runtime allocation) -----------
__device__ float g_deg[NSEG];
__device__ int   g_cnt[NSEG];
__device__ int   g_cur[NSEG];
__device__ int   g_start[NSEG + 1];
__device__ int   g_perm[E_EDGES];
__device__ float g_upd [NSEG * DDIM];
__device__ float g_feat[NSEG * DDIM];
__device__ float g_Q   [NSEG * DDIM];
__device__ float g_K   [NSEG * DDIM];
__device__ float g_S[(size_t)NRH * NNODE * NNODE];   // 512 MB: E = exp(s)
__device__ float g_Z[NRH * NNODE];                   // softmax partition sums
__device__ float g_val[NSEL];
__device__ unsigned int g_minBits, g_maxBits;

// fast exp on the FMA pipe. rel err ~1e-7.
__device__ __forceinline__ float fexp(float x) {
    x = fmaxf(x, -87.0f);
    float t  = x * 1.4426950408889634f;
    float fi = rintf(t);
    float f  = t - fi;
    float p  = 1.5403530393e-4f;
    p = fmaf(p, f, 1.3333558146e-3f);
    p = fmaf(p, f, 9.6181291076e-3f);
    p = fmaf(p, f, 5.5504108664e-2f);
    p = fmaf(p, f, 2.4022650696e-1f);
    p = fmaf(p, f, 6.9314718056e-1f);
    p = fmaf(p, f, 1.0f);
    int j = (int)fi;
    return p * __int_as_float((j + 127) << 23);
}

// ---------------- 3xTF32 helpers ----------------
__device__ __forceinline__ void tf32_split(float x, unsigned& hi, unsigned& lo) {
    unsigned h; asm("cvt.rna.tf32.f32 %0, %1;\n" : "=r"(h) : "f"(x));
    float r = x - __uint_as_float(h);
    unsigned l; asm("cvt.rna.tf32.f32 %0, %1;\n" : "=r"(l) : "f"(r));
    hi = h; lo = l;
}

__device__ __forceinline__ void mma_tf32(float* c, const unsigned* a, const unsigned* b) {
    asm volatile(
        "mma.sync.aligned.m16n8k8.row.col.f32.tf32.tf32.f32 "
        "{%0,%1,%2,%3}, {%4,%5,%6,%7}, {%8,%9}, {%0,%1,%2,%3};\n"
        : "+f"(c[0]), "+f"(c[1]), "+f"(c[2]), "+f"(c[3])
        : "r"(a[0]), "r"(a[1]), "r"(a[2]), "r"(a[3]), "r"(b[0]), "r"(b[1]));
}

// ---------------- 0: init ----------------
__global__ void k_zero() {
    int t = blockIdx.x * blockDim.x + threadIdx.x;
    if (t < NSEG) { g_deg[t] = 0.f; g_cnt[t] = 0; g_cur[t] = 0; }
    if (t == 0) { g_minBits = 0x7f7fffffu; g_maxBits = 0u; }
}

// ---------------- 1: histogram + degree ----------------
__global__ void k_hist(const int* __restrict__ el, const float* __restrict__ ew) {
    int e = blockIdx.x * blockDim.x + threadIdx.x;
    if (e < E_EDGES) {
        int seg = el[3 * e + 1] * NREL + el[3 * e + 2];
        atomicAdd(&g_cnt[seg], 1);
        atomicAdd(&g_deg[seg], ew[e]);
    }
}

// ---------------- 2: exclusive scan of 8192 counts (one block) -------------
__global__ void k_scan() {
    __shared__ int part[1024];
    int tid = threadIdx.x;
    int base = tid * 8;
    int loc[8]; int s = 0;
    #pragma unroll
    for (int j = 0; j < 8; j++) { loc[j] = g_cnt[base + j]; s += loc[j]; }
    part[tid] = s; __syncthreads();
    for (int off = 1; off < 1024; off <<= 1) {
        int v = part[tid];
        if (tid >= off) v += part[tid - off];
        __syncthreads(); part[tid] = v; __syncthreads();
    }
    int run = part[tid] - s;
    #pragma unroll
    for (int j = 0; j < 8; j++) { g_start[base + j] = run; run += loc[j]; }
    if (tid == 1023) g_start[NSEG] = part[1023];
}

// ---------------- 3: scatter edge ids into segment bins --------------------
__global__ void k_scatter(const int* __restrict__ el) {
    int e = blockIdx.x * blockDim.x + threadIdx.x;
    if (e < E_EDGES) {
        int seg = el[3 * e + 1] * NREL + el[3 * e + 2];
        int pos = g_start[seg] + atomicAdd(&g_cur[seg], 1);
        g_perm[pos] = e;
    }
}

// ---------------- 4: per-segment weighted feature sum ----------------------
__global__ void k_update(const int* __restrict__ el, const float* __restrict__ ew,
                         const float* __restrict__ nf) {
    __shared__ int   s_in[128];
    __shared__ float s_c[128];
    int seg = blockIdx.x, tid = threadIdx.x;
    int s0 = g_start[seg], s1 = g_start[seg + 1];
    float inv = 1.f / (g_deg[seg] + EPSV);
    float4 a0 = make_float4(0.f, 0.f, 0.f, 0.f);
    float4 a1 = make_float4(0.f, 0.f, 0.f, 0.f);
    for (int p0 = s0; p0 < s1; p0 += 128) {
        int p = p0 + tid;
        if (p < s1) {
            int e = g_perm[p];
            s_in[tid] = el[3 * e];
            s_c[tid]  = ew[e] * inv;
        }
        __syncthreads();
        int cnt = min(128, s1 - p0);
        int q = 0;
        for (; q + 1 < cnt; q += 2) {
            float c0 = s_c[q], c1 = s_c[q + 1];
            float4 va = ((const float4*)(nf + (size_t)s_in[q]     * DDIM))[tid];
            float4 vb = ((const float4*)(nf + (size_t)s_in[q + 1] * DDIM))[tid];
            a0.x = fmaf(c0, va.x, a0.x); a0.y = fmaf(c0, va.y, a0.y);
            a0.z = fmaf(c0, va.z, a0.z); a0.w = fmaf(c0, va.w, a0.w);
            a1.x = fmaf(c1, vb.x, a1.x); a1.y = fmaf(c1, vb.y, a1.y);
            a1.z = fmaf(c1, vb.z, a1.z); a1.w = fmaf(c1, vb.w, a1.w);
        }
        if (q < cnt) {
            float c0 = s_c[q];
            float4 va = ((const float4*)(nf + (size_t)s_in[q] * DDIM))[tid];
            a0.x = fmaf(c0, va.x, a0.x); a0.y = fmaf(c0, va.y, a0.y);
            a0.z = fmaf(c0, va.z, a0.z); a0.w = fmaf(c0, va.w, a0.w);
        }
        __syncthreads();
    }
    float4 o;
    o.x = a0.x + a1.x; o.y = a0.y + a1.y; o.z = a0.z + a1.z; o.w = a0.w + a1.w;
    ((float4*)(g_upd + (size_t)seg * DDIM))[tid] = o;
}

// ------ 3xTF32 GEMM: C(8192x512) = act(A(8192x512) @ W(512x512)^T + b) -----
__device__ __forceinline__ void gemm_tc(const float* __restrict__ A,
                                        const float* __restrict__ W,
                                        const float* __restrict__ bias,
                                        float* __restrict__ C, bool relu) {
    extern __shared__ unsigned su[];
    unsigned* Ah = su;
    unsigned* Al = su + 128 * GS;
    unsigned* Wh = su + 2 * 128 * GS;
    unsigned* Wl = su + 3 * 128 * GS;
    int tid = threadIdx.x;
    int wid = tid >> 5, lane = tid & 31;
    int gid = lane >> 2, tig = lane & 3;
    int warpM = wid >> 2, warpN = wid & 3;
    int ibase = blockIdx.y * 128, jbase = blockIdx.x * 128;

    float c[4][4][4];
    #pragma unroll
    for (int mt = 0; mt < 4; mt++)
        #pragma unroll
        for (int nt = 0; nt < 4; nt++)
            #pragma unroll
            for (int j = 0; j < 4; j++) c[mt][nt][j] = 0.f;

    for (int kc = 0; kc < DDIM; kc += 32) {
        __syncthreads();
        #pragma unroll
        for (int l = 0; l < 4; l++) {
            int u = l * 256 + tid;
            int row = u >> 3, c4 = (u & 7) * 4;
            float4 v = *(const float4*)(A + (size_t)(ibase + row) * DDIM + kc + c4);
            unsigned h0, l0;
            tf32_split(v.x, h0, l0); Ah[row*GS + c4 + 0] = h0; Al[row*GS + c4 + 0] = l0;
            tf32_split(v.y, h0, l0); Ah[row*GS + c4 + 1] = h0; Al[row*GS + c4 + 1] = l0;
            tf32_split(v.z, h0, l0); Ah[row*GS + c4 + 2] = h0; Al[row*GS + c4 + 2] = l0;
            tf32_split(v.w, h0, l0); Ah[row*GS + c4 + 3] = h0; Al[row*GS + c4 + 3] = l0;
            float4 w = *(const float4*)(W + (size_t)(jbase + row) * DDIM + kc + c4);
            tf32_split(w.x, h0, l0); Wh[row*GS + c4 + 0] = h0; Wl[row*GS + c4 + 0] = l0;
            tf32_split(w.y, h0, l0); Wh[row*GS + c4 + 1] = h0; Wl[row*GS + c4 + 1] = l0;
            tf32_split(w.z, h0, l0); Wh[row*GS + c4 + 2] = h0; Wl[row*GS + c4 + 2] = l0;
            tf32_split(w.w, h0, l0); Wh[row*GS + c4 + 3] = h0; Wl[row*GS + c4 + 3] = l0;
        }
        __syncthreads();
        #pragma unroll
        for (int k8 = 0; k8 < 32; k8 += 8) {
            unsigned ah[4][4], al[4][4];
            #pragma unroll
            for (int mt = 0; mt < 4; mt++) {
                int r0 = (warpM * 64 + mt * 16 + gid) * GS + k8 + tig;
                ah[mt][0] = Ah[r0];             al[mt][0] = Al[r0];
                ah[mt][1] = Ah[r0 + 8 * GS];    al[mt][1] = Al[r0 + 8 * GS];
                ah[mt][2] = Ah[r0 + 4];         al[mt][2] = Al[r0 + 4];
                ah[mt][3] = Ah[r0 + 8 * GS + 4];al[mt][3] = Al[r0 + 8 * GS + 4];
            }
            #pragma unroll
            for (int nt = 0; nt < 4; nt++) {
                int q0 = (warpN * 32 + nt * 8 + gid) * GS + k8 + tig;
                unsigned bh[2], bl[2];
                bh[0] = Wh[q0]; bh[1] = Wh[q0 + 4];
                bl[0] = Wl[q0]; bl[1] = Wl[q0 + 4];
                #pragma unroll
                for (int mt = 0; mt < 4; mt++) {
                    mma_tf32(c[mt][nt], al[mt], bh);
                    mma_tf32(c[mt][nt], ah[mt], bl);
                    mma_tf32(c[mt][nt], ah[mt], bh);
                }
            }
        }
    }
    #pragma unroll
    for (int mt = 0; mt < 4; mt++) {
        int gi = ibase + warpM * 64 + mt * 16 + gid;
        #pragma unroll
        for (int nt = 0; nt < 4; nt++) {
            int gj = jbase + warpN * 32 + nt * 8 + 2 * tig;
            float2 bb = *(const float2*)(bias + gj);
            float v0 = c[mt][nt][0] + bb.x, v1 = c[mt][nt][1] + bb.y;
            float v2 = c[mt][nt][2] + bb.x, v3 = c[mt][nt][3] + bb.y;
            if (relu) { v0 = fmaxf(v0, 0.f); v1 = fmaxf(v1, 0.f);
                        v2 = fmaxf(v2, 0.f); v3 = fmaxf(v3, 0.f); }
            float2 o0; o0.x = v0; o0.y = v1;
            float2 o1; o1.x = v2; o1.y = v3;
            *(float2*)(C + (size_t)gi * DDIM + gj)        = o0;
            *(float2*)(C + (size_t)(gi + 8) * DDIM + gj)  = o1;
        }
    }
}

__global__ void __launch_bounds__(256) k_gemm_feat(const float* W, const float* b) { gemm_tc(g_upd,  W, b, g_feat, true);  }
__global__ void __launch_bounds__(256) k_gemm_qk(const float* Wq, const float* bq,
                                                 const float* Wk, const float* bk) {
    if (blockIdx.z == 0) gemm_tc(g_feat, Wq, bq, g_Q, false);
    else                 gemm_tc(g_feat, Wk, bk, g_K, false);
}

// ------ 3xTF32 scores (persistent-m): E[rh][n][m] = exp(QK^T/4), Z direct --
// grid (16 n-tiles, 32 rh); block owns whole row -> Z with no atomics.
__global__ void __launch_bounds__(256) k_scores() {
    extern __shared__ unsigned su[];
    unsigned* Qh = su;                   // [128][KS]
    unsigned* Ql = su + 128 * KS;
    unsigned* Kh = su + 2 * 128 * KS;
    unsigned* Kl = su + 3 * 128 * KS;
    __shared__ float zsm[128];
    int tid = threadIdx.x;
    int wid = tid >> 5, lane = tid & 31;
    int gid = lane >> 2, tig = lane & 3;
    int warpM = wid >> 2, warpN = wid & 3;
    int nbase = blockIdx.x * 128;
    int rh = blockIdx.y;
    int r = rh >> 3, h = rh & 7;
    const float* Qb = g_Q + (size_t)r * NNODE * DDIM + h * DH;
    const float* Kb = g_K + (size_t)r * NNODE * DDIM + h * DH;

    if (tid < 128) zsm[tid] = 0.f;

    // load + split Q tile once: 128 rows x 64 cols
    #pragma unroll
    for (int l = 0; l < 8; l++) {
        int u = l * 256 + tid;               // 0..2047 float4 units
        int row = u >> 4, c4 = (u & 15) * 4;
        float4 v = *(const float4*)(Qb + (size_t)(nbase + row) * DDIM + c4);
        unsigned h0, l0;
        tf32_split(v.x, h0, l0); Qh[row*KS + c4 + 0] = h0; Ql[row*KS + c4 + 0] = l0;
        tf32_split(v.y, h0, l0); Qh[row*KS + c4 + 1] = h0; Ql[row*KS + c4 + 1] = l0;
        tf32_split(v.z, h0, l0); Qh[row*KS + c4 + 2] = h0; Ql[row*KS + c4 + 2] = l0;
        tf32_split(v.w, h0, l0); Qh[row*KS + c4 + 3] = h0; Ql[row*KS + c4 + 3] = l0;
    }

    float zacc[4][2];
    #pragma unroll
    for (int mt = 0; mt < 4; mt++) { zacc[mt][0] = 0.f; zacc[mt][1] = 0.f; }

    for (int mt16 = 0; mt16 < 16; mt16++) {
        int mbase = mt16 * 128;
        __syncthreads();   // Q visible (iter 0) / Kh reuse safe (iters >0)
        #pragma unroll
        for (int l = 0; l < 8; l++) {
            int u = l * 256 + tid;
            int row = u >> 4, c4 = (u & 15) * 4;
            float4 v = *(const float4*)(Kb + (size_t)(mbase + row) * DDIM + c4);
            unsigned h0, l0;
            tf32_split(v.x, h0, l0); Kh[row*KS + c4 + 0] = h0; Kl[row*KS + c4 + 0] = l0;
            tf32_split(v.y, h0, l0); Kh[row*KS + c4 + 1] = h0; Kl[row*KS + c4 + 1] = l0;
            tf32_split(v.z, h0, l0); Kh[row*KS + c4 + 2] = h0; Kl[row*KS + c4 + 2] = l0;
            tf32_split(v.w, h0, l0); Kh[row*KS + c4 + 3] = h0; Kl[row*KS + c4 + 3] = l0;
        }
        __syncthreads();

        float c[4][4][4];
        #pragma unroll
        for (int mt = 0; mt < 4; mt++)
            #pragma unroll
            for (int nt = 0; nt < 4; nt++)
                #pragma unroll
                for (int j = 0; j < 4; j++) c[mt][nt][j] = 0.f;

        #pragma unroll
        for (int k8 = 0; k8 < 64; k8 += 8) {
            unsigned ah[4][4], al[4][4];
            #pragma unroll
            for (int mt = 0; mt < 4; mt++) {
                int r0 = (warpM * 64 + mt * 16 + gid) * KS + k8 + tig;
                ah[mt][0] = Qh[r0];             al[mt][0] = Ql[r0];
                ah[mt][1] = Qh[r0 + 8 * KS];    al[mt][1] = Ql[r0 + 8 * KS];
                ah[mt][2] = Qh[r0 + 4];         al[mt][2] = Ql[r0 + 4];
                ah[mt][3] = Qh[r0 + 8 * KS + 4];al[mt][3] = Ql[r0 + 8 * KS + 4];
            }
            #pragma unroll
            for (int nt = 0; nt < 4; nt++) {
                int q0 = (warpN * 32 + nt * 8 + gid) * KS + k8 + tig;
                unsigned bh[2], bl[2];
                bh[0] = Kh[q0]; bh[1] = Kh[q0 + 4];
                bl[0] = Kl[q0]; bl[1] = Kl[q0 + 4];
                #pragma unroll
                for (int mt = 0; mt < 4; mt++) {
                    mma_tf32(c[mt][nt], al[mt], bh);
                    mma_tf32(c[mt][nt], ah[mt], bl);
                    mma_tf32(c[mt][nt], ah[mt], bh);
                }
            }
        }

        // epilogue: E = exp(s/4), store, accumulate row sums in registers
        #pragma unroll
        for (int mt = 0; mt < 4; mt++) {
            int ni = nbase + warpM * 64 + mt * 16 + gid;
            float* So = g_S + ((size_t)rh * NNODE + ni) * NNODE;
            float pl = 0.f, pu = 0.f;
            #pragma unroll
            for (int nt = 0; nt < 4; nt++) {
                int mj = mbase + warpN * 32 + nt * 8 + 2 * tig;
                float e00 = fexp(c[mt][nt][0] * 0.25f);
                float e01 = fexp(c[mt][nt][1] * 0.25f);
                float e10 = fexp(c[mt][nt][2] * 0.25f);
                float e11 = fexp(c[mt][nt][3] * 0.25f);
                float2 o0; o0.x = e00; o0.y = e01;
                float2 o1; o1.x = e10; o1.y = e11;
                *(float2*)(So + mj)                     = o0;
                *(float2*)(So + (size_t)8 * NNODE + mj) = o1;
                pl += e00 + e01;
                pu += e10 + e11;
            }
            zacc[mt][0] += pl;
            zacc[mt][1] += pu;
        }
    }

    // reduce Z: tig lanes (same row, different m cols) then cross-warpN via smem
    #pragma unroll
    for (int mt = 0; mt < 4; mt++) {
        float pl = zacc[mt][0], pu = zacc[mt][1];
        pl += __shfl_xor_sync(~0u, pl, 1); pl += __shfl_xor_sync(~0u, pl, 2);
        pu += __shfl_xor_sync(~0u, pu, 1); pu += __shfl_xor_sync(~0u, pu, 2);
        if (tig == 0) {
            atomicAdd(&zsm[warpM * 64 + mt * 16 + gid],     pl);
            atomicAdd(&zsm[warpM * 64 + mt * 16 + gid + 8], pu);
        }
    }
    __syncthreads();
    if (tid < 128) g_Z[rh * NNODE + nbase + tid] = zsm[tid];
}

// ---------------- selection: streaming A accumulation + exact top-3 --------
__global__ void __launch_bounds__(256) k_select(float* __restrict__ out) {
    __shared__ float sA[2048];
    __shared__ float sW[8];  __shared__ int sWi[8];
    __shared__ float topv[5]; __shared__ int topi[5];
    __shared__ int scount;
    int tid = threadIdx.x, lane = tid & 31, wid = tid >> 5;
    int b = blockIdx.x;
    int r = b >> 11, n = b & (NNODE - 1);
    const float* Sb = g_S + ((size_t)r * NHEAD * NNODE + n) * NNODE;

    float iz[NHEAD];
    #pragma unroll
    for (int h = 0; h < NHEAD; h++)
        iz[h] = 0.125f / g_Z[(r * NHEAD + h) * NNODE + n];

    float acc[8];
    #pragma unroll
    for (int l = 0; l < 8; l++) acc[l] = 0.f;

    #pragma unroll
    for (int h = 0; h < NHEAD; h++) {
        const float* row = Sb + (size_t)h * NNODE * NNODE;
        float4 v0 = *(const float4*)(row + 4 * tid);
        float4 v1 = *(const float4*)(row + 4 * (256 + tid));
        float z = iz[h];
        acc[0] = fmaf(v0.x, z, acc[0]); acc[1] = fmaf(v0.y, z, acc[1]);
        acc[2] = fmaf(v0.z, z, acc[2]); acc[3] = fmaf(v0.w, z, acc[3]);
        acc[4] = fmaf(v1.x, z, acc[4]); acc[5] = fmaf(v1.y, z, acc[5]);
        acc[6] = fmaf(v1.z, z, acc[6]); acc[7] = fmaf(v1.w, z, acc[7]);
    }

    *(float4*)(sA + 4 * tid)         = make_float4(acc[0], acc[1], acc[2], acc[3]);
    *(float4*)(sA + 4 * (256 + tid)) = make_float4(acc[4], acc[5], acc[6], acc[7]);
    __syncthreads();

    for (int s = 0; s < 5; s++) {
        float bv = -2.f; int bi = 0;
        #pragma unroll
        for (int l = 0; l < 8; l++) {
            int m = l * 256 + tid;
            float v = sA[m];
            if (v > bv || (v == bv && m < bi)) { bv = v; bi = m; }
        }
        #pragma unroll
        for (int o = 16; o; o >>= 1) {
            float v2 = __shfl_xor_sync(~0u, bv, o);
            int   i2 = __shfl_xor_sync(~0u, bi, o);
            if (v2 > bv || (v2 == bv && i2 < bi)) { bv = v2; bi = i2; }
        }
        if (lane == 0) { sW[wid] = bv; sWi[wid] = bi; }
        __syncthreads();
        if (tid == 0) {
            float fv = sW[0]; int fi = sWi[0];
            #pragma unroll
            for (int w = 1; w < 8; w++) {
                if (sW[w] > fv || (sW[w] == fv && sWi[w] < fi)) { fv = sW[w]; fi = sWi[w]; }
            }
            topv[s] = fv; topi[s] = fi; sA[fi] = -1.f;
        }
        __syncthreads();
    }
    if (tid == 0) {
        #pragma unroll
        for (int s = 0; s < 5; s++) sA[topi[s]] = topv[s];
        scount = 0;
    }
    __syncthreads();

    float fifth = topv[4];
    int c = 0;
    #pragma unroll
    for (int l = 0; l < 8; l++) if (sA[l * 256 + tid] == fifth) c++;
    if (c) atomicAdd(&scount, c);
    __syncthreads();

    if (tid == 0) {
        int sel[3]; float val[3];
        int cnt = scount;
        if (cnt <= 3) {
            sel[0] = topi[0]; sel[1] = topi[1]; sel[2] = topi[2];
            val[0] = topv[0]; val[1] = topv[1]; val[2] = topv[2];
        } else {
            int mg = 0;
            while (mg < 5 && topv[mg] > fifth) mg++;
            int bd[3] = {1 << 29, 1 << 29, 1 << 29};
            int bs[3] = {0, 0, 0};
            #define CONSIDER(IDX) { int d_ = (IDX) >= n ? (IDX) - n : n - (IDX);            \
                if (d_ < bd[0]) { bd[2]=bd[1]; bs[2]=bs[1]; bd[1]=bd[0]; bs[1]=bs[0];       \
                                  bd[0]=d_; bs[0]=(IDX); }                                   \
                else if (d_ < bd[1]) { bd[2]=bd[1]; bs[2]=bs[1]; bd[1]=d_; bs[1]=(IDX); }    \
                else if (d_ < bd[2]) { bd[2]=d_; bs[2]=(IDX); } }
            for (int p = 0; p < mg; p++) CONSIDER(topi[p]);
            int taken = mg;
            for (int idx = 0; idx < NNODE && taken < cnt; idx++)
                if (sA[idx] == fifth) { CONSIDER(idx); taken++; }
            #undef CONSIDER
            sel[0] = bs[0]; sel[1] = bs[1]; sel[2] = bs[2];
            val[0] = sA[bs[0]]; val[1] = sA[bs[1]]; val[2] = sA[bs[2]];
        }
        size_t ebase = ((size_t)r * NNODE + n) * 3;
        #pragma unroll
        for (int k = 0; k < 3; k++) {
            size_t e = ebase + k;
            out[e * 3 + 0] = (float)n;
            out[e * 3 + 1] = (float)sel[k];
            out[e * 3 + 2] = (float)r;
            g_val[e] = val[k];
            atomicMin(&g_minBits, __float_as_uint(val[k]));
            atomicMax(&g_maxBits, __float_as_uint(val[k]));
        }
    }
}

// ---------------- final normalize ----------------
__global__ void k_norm(float* __restrict__ out) {
    int e = blockIdx.x * blockDim.x + threadIdx.x;
    if (e < NSEL) {
        float mn = __uint_as_float(g_minBits);
        float mx = __uint_as_float(g_maxBits);
        out[NSEL * 3 + e] = (g_val[e] - mn) / (mx - mn + EPSV);
    }
}

// ---------------- host launcher ----------------
extern "C" void kernel_launch(void* const* d_in, const int* in_sizes, int n_in,
                              void* d_out, int out_size) {
    const float* nf = (const float*)d_in[0];
    const int*   el = (const int*)  d_in[1];
    const float* ew = (const float*)d_in[2];
    const float* Wl = (const float*)d_in[3];
    const float* bl = (const float*)d_in[4];
    const float* Wq = (const float*)d_in[5];
    const float* bq = (const float*)d_in[6];
    const float* Wk = (const float*)d_in[7];
    const float* bk = (const float*)d_in[8];
    float* out = (float*)d_out;

    const int MMSM = 4 * 128 * GS * 4;   // 73728 bytes (GEMMs)
    const int SCSM = 4 * 128 * KS * 4;   // 139264 bytes (scores)
    cudaFuncSetAttribute(k_gemm_feat, cudaFuncAttributeMaxDynamicSharedMemorySize, MMSM);
    cudaFuncSetAttribute(k_gemm_qk,   cudaFuncAttributeMaxDynamicSharedMemorySize, MMSM);
    cudaFuncSetAttribute(k_scores,    cudaFuncAttributeMaxDynamicSharedMemorySize, SCSM);

    k_zero<<<32, 256>>>();
    k_hist<<<E_EDGES / 256, 256>>>(el, ew);
    k_scan<<<1, 1024>>>();
    k_scatter<<<E_EDGES / 256, 256>>>(el);
    k_update<<<NSEG, 128>>>(el, ew, nf);
    k_gemm_feat<<<dim3(4, 64), 256, MMSM>>>(Wl, bl);
    k_gemm_qk  <<<dim3(4, 64, 2), 256, MMSM>>>(Wq, bq, Wk, bk);
    k_scores<<<dim3(16, NRH), 256, SCSM>>>();
    k_select<<<NSEG, 256>>>(out);
    k_norm<<<NSEL / 256, 256>>>(out);
}

// round 9
// speedup vs baseline: 1.2224x; 1.2224x over previous
#include <cuda_runtime.h>
#include <math.h>

#define E_EDGES 262144
#define NNODE   2048
#define NREL    4
#define NSEG    8192          /* NNODE*NREL */
#define DDIM    512
#define NHEAD   8
#define DH      64
#define EPSV    1e-10f
#define NSEL    24576         /* NREL*NNODE*3 */
#define GS      36            /* smem stride (floats) for mma tiles */
#define NRH     32            /* NREL*NHEAD */

// ---------------- device scratch (static; no runtime allocation) -----------
__device__ float g_deg[NSEG];
__device__ int   g_cnt[NSEG];
__device__ int   g_cur[NSEG];
__device__ int   g_start[NSEG + 1];
__device__ int   g_perm[E_EDGES];
__device__ float g_upd [NSEG * DDIM];
__device__ float g_feat[NSEG * DDIM];
__device__ float g_Q   [NSEG * DDIM];
__device__ float g_K   [NSEG * DDIM];
__device__ float g_S[(size_t)NRH * NNODE * NNODE];   // 512 MB: E = exp(s)
__device__ float g_Z[NRH * NNODE];                   // softmax partition sums
__device__ float g_val[NSEL];
__device__ unsigned int g_minBits, g_maxBits;

// ---------------- 3xTF32 helpers ----------------
__device__ __forceinline__ void tf32_split(float x, unsigned& hi, unsigned& lo) {
    unsigned h; asm("cvt.rna.tf32.f32 %0, %1;\n" : "=r"(h) : "f"(x));
    float r = x - __uint_as_float(h);
    unsigned l; asm("cvt.rna.tf32.f32 %0, %1;\n" : "=r"(l) : "f"(r));
    hi = h; lo = l;
}

__device__ __forceinline__ void mma_tf32(float* c, const unsigned* a, const unsigned* b) {
    asm volatile(
        "mma.sync.aligned.m16n8k8.row.col.f32.tf32.tf32.f32 "
        "{%0,%1,%2,%3}, {%4,%5,%6,%7}, {%8,%9}, {%0,%1,%2,%3};\n"
        : "+f"(c[0]), "+f"(c[1]), "+f"(c[2]), "+f"(c[3])
        : "r"(a[0]), "r"(a[1]), "r"(a[2]), "r"(a[3]), "r"(b[0]), "r"(b[1]));
}

// ---------------- 0: init ----------------
__global__ void k_zero() {
    int t = blockIdx.x * blockDim.x + threadIdx.x;
    if (t < NSEG) { g_deg[t] = 0.f; g_cnt[t] = 0; g_cur[t] = 0; }
    if (t < NRH * NNODE) g_Z[t] = 0.f;
    if (t == 0) { g_minBits = 0x7f7fffffu; g_maxBits = 0u; }
}

// ---------------- 1: histogram + degree ----------------
__global__ void k_hist(const int* __restrict__ el, const float* __restrict__ ew) {
    int e = blockIdx.x * blockDim.x + threadIdx.x;
    if (e < E_EDGES) {
        int seg = el[3 * e + 1] * NREL + el[3 * e + 2];
        atomicAdd(&g_cnt[seg], 1);
        atomicAdd(&g_deg[seg], ew[e]);
    }
}

// ---------------- 2: exclusive scan of 8192 counts (one block) -------------
__global__ void k_scan() {
    __shared__ int part[1024];
    int tid = threadIdx.x;
    int base = tid * 8;
    int loc[8]; int s = 0;
    #pragma unroll
    for (int j = 0; j < 8; j++) { loc[j] = g_cnt[base + j]; s += loc[j]; }
    part[tid] = s; __syncthreads();
    for (int off = 1; off < 1024; off <<= 1) {
        int v = part[tid];
        if (tid >= off) v += part[tid - off];
        __syncthreads(); part[tid] = v; __syncthreads();
    }
    int run = part[tid] - s;
    #pragma unroll
    for (int j = 0; j < 8; j++) { g_start[base + j] = run; run += loc[j]; }
    if (tid == 1023) g_start[NSEG] = part[1023];
}

// ---------------- 3: scatter edge ids into segment bins --------------------
__global__ void k_scatter(const int* __restrict__ el) {
    int e = blockIdx.x * blockDim.x + threadIdx.x;
    if (e < E_EDGES) {
        int seg = el[3 * e + 1] * NREL + el[3 * e + 2];
        int pos = g_start[seg] + atomicAdd(&g_cur[seg], 1);
        g_perm[pos] = e;
    }
}

// ---------------- 4: per-segment weighted feature sum ----------------------
__global__ void k_update(const int* __restrict__ el, const float* __restrict__ ew,
                         const float* __restrict__ nf) {
    __shared__ int   s_in[128];
    __shared__ float s_c[128];
    int seg = blockIdx.x, tid = threadIdx.x;
    int s0 = g_start[seg], s1 = g_start[seg + 1];
    float inv = 1.f / (g_deg[seg] + EPSV);
    float4 a0 = make_float4(0.f, 0.f, 0.f, 0.f);
    float4 a1 = make_float4(0.f, 0.f, 0.f, 0.f);
    for (int p0 = s0; p0 < s1; p0 += 128) {
        int p = p0 + tid;
        if (p < s1) {
            int e = g_perm[p];
            s_in[tid] = el[3 * e];
            s_c[tid]  = ew[e] * inv;
        }
        __syncthreads();
        int cnt = min(128, s1 - p0);
        int q = 0;
        for (; q + 1 < cnt; q += 2) {
            float c0 = s_c[q], c1 = s_c[q + 1];
            float4 va = ((const float4*)(nf + (size_t)s_in[q]     * DDIM))[tid];
            float4 vb = ((const float4*)(nf + (size_t)s_in[q + 1] * DDIM))[tid];
            a0.x = fmaf(c0, va.x, a0.x); a0.y = fmaf(c0, va.y, a0.y);
            a0.z = fmaf(c0, va.z, a0.z); a0.w = fmaf(c0, va.w, a0.w);
            a1.x = fmaf(c1, vb.x, a1.x); a1.y = fmaf(c1, vb.y, a1.y);
            a1.z = fmaf(c1, vb.z, a1.z); a1.w = fmaf(c1, vb.w, a1.w);
        }
        if (q < cnt) {
            float c0 = s_c[q];
            float4 va = ((const float4*)(nf + (size_t)s_in[q] * DDIM))[tid];
            a0.x = fmaf(c0, va.x, a0.x); a0.y = fmaf(c0, va.y, a0.y);
            a0.z = fmaf(c0, va.z, a0.z); a0.w = fmaf(c0, va.w, a0.w);
        }
        __syncthreads();
    }
    float4 o;
    o.x = a0.x + a1.x; o.y = a0.y + a1.y; o.z = a0.z + a1.z; o.w = a0.w + a1.w;
    ((float4*)(g_upd + (size_t)seg * DDIM))[tid] = o;
}

// ------ 3xTF32 GEMM: C(8192x512) = act(A(8192x512) @ W(512x512)^T + b) -----
__device__ __forceinline__ void gemm_tc(const float* __restrict__ A,
                                        const float* __restrict__ W,
                                        const float* __restrict__ bias,
                                        float* __restrict__ C, bool relu) {
    extern __shared__ unsigned su[];
    unsigned* Ah = su;
    unsigned* Al = su + 128 * GS;
    unsigned* Wh = su + 2 * 128 * GS;
    unsigned* Wl = su + 3 * 128 * GS;
    int tid = threadIdx.x;
    int wid = tid >> 5, lane = tid & 31;
    int gid = lane >> 2, tig = lane & 3;
    int warpM = wid >> 2, warpN = wid & 3;
    int ibase = blockIdx.y * 128, jbase = blockIdx.x * 128;

    float c[4][4][4];
    #pragma unroll
    for (int mt = 0; mt < 4; mt++)
        #pragma unroll
        for (int nt = 0; nt < 4; nt++)
            #pragma unroll
            for (int j = 0; j < 4; j++) c[mt][nt][j] = 0.f;

    for (int kc = 0; kc < DDIM; kc += 32) {
        __syncthreads();
        #pragma unroll
        for (int l = 0; l < 4; l++) {
            int u = l * 256 + tid;
            int row = u >> 3, c4 = (u & 7) * 4;
            float4 v = *(const float4*)(A + (size_t)(ibase + row) * DDIM + kc + c4);
            unsigned h0, l0;
            tf32_split(v.x, h0, l0); Ah[row*GS + c4 + 0] = h0; Al[row*GS + c4 + 0] = l0;
            tf32_split(v.y, h0, l0); Ah[row*GS + c4 + 1] = h0; Al[row*GS + c4 + 1] = l0;
            tf32_split(v.z, h0, l0); Ah[row*GS + c4 + 2] = h0; Al[row*GS + c4 + 2] = l0;
            tf32_split(v.w, h0, l0); Ah[row*GS + c4 + 3] = h0; Al[row*GS + c4 + 3] = l0;
            float4 w = *(const float4*)(W + (size_t)(jbase + row) * DDIM + kc + c4);
            tf32_split(w.x, h0, l0); Wh[row*GS + c4 + 0] = h0; Wl[row*GS + c4 + 0] = l0;
            tf32_split(w.y, h0, l0); Wh[row*GS + c4 + 1] = h0; Wl[row*GS + c4 + 1] = l0;
            tf32_split(w.z, h0, l0); Wh[row*GS + c4 + 2] = h0; Wl[row*GS + c4 + 2] = l0;
            tf32_split(w.w, h0, l0); Wh[row*GS + c4 + 3] = h0; Wl[row*GS + c4 + 3] = l0;
        }
        __syncthreads();
        #pragma unroll
        for (int k8 = 0; k8 < 32; k8 += 8) {
            unsigned ah[4][4], al[4][4];
            #pragma unroll
            for (int mt = 0; mt < 4; mt++) {
                int r0 = (warpM * 64 + mt * 16 + gid) * GS + k8 + tig;
                ah[mt][0] = Ah[r0];             al[mt][0] = Al[r0];
                ah[mt][1] = Ah[r0 + 8 * GS];    al[mt][1] = Al[r0 + 8 * GS];
                ah[mt][2] = Ah[r0 + 4];         al[mt][2] = Al[r0 + 4];
                ah[mt][3] = Ah[r0 + 8 * GS + 4];al[mt][3] = Al[r0 + 8 * GS + 4];
            }
            #pragma unroll
            for (int nt = 0; nt < 4; nt++) {
                int q0 = (warpN * 32 + nt * 8 + gid) * GS + k8 + tig;
                unsigned bh[2], bl[2];
                bh[0] = Wh[q0]; bh[1] = Wh[q0 + 4];
                bl[0] = Wl[q0]; bl[1] = Wl[q0 + 4];
                #pragma unroll
                for (int mt = 0; mt < 4; mt++) {
                    mma_tf32(c[mt][nt], al[mt], bh);
                    mma_tf32(c[mt][nt], ah[mt], bl);
                    mma_tf32(c[mt][nt], ah[mt], bh);
                }
            }
        }
    }
    #pragma unroll
    for (int mt = 0; mt < 4; mt++) {
        int gi = ibase + warpM * 64 + mt * 16 + gid;
        #pragma unroll
        for (int nt = 0; nt < 4; nt++) {
            int gj = jbase + warpN * 32 + nt * 8 + 2 * tig;
            float2 bb = *(const float2*)(bias + gj);
            float v0 = c[mt][nt][0] + bb.x, v1 = c[mt][nt][1] + bb.y;
            float v2 = c[mt][nt][2] + bb.x, v3 = c[mt][nt][3] + bb.y;
            if (relu) { v0 = fmaxf(v0, 0.f); v1 = fmaxf(v1, 0.f);
                        v2 = fmaxf(v2, 0.f); v3 = fmaxf(v3, 0.f); }
            float2 o0; o0.x = v0; o0.y = v1;
            float2 o1; o1.x = v2; o1.y = v3;
            *(float2*)(C + (size_t)gi * DDIM + gj)        = o0;
            *(float2*)(C + (size_t)(gi + 8) * DDIM + gj)  = o1;
        }
    }
}

__global__ void __launch_bounds__(256) k_gemm_feat(const float* W, const float* b) { gemm_tc(g_upd,  W, b, g_feat, true);  }
__global__ void __launch_bounds__(256) k_gemm_qk(const float* Wq, const float* bq,
                                                 const float* Wk, const float* bk) {
    if (blockIdx.z == 0) gemm_tc(g_feat, Wq, bq, g_Q, false);
    else                 gemm_tc(g_feat, Wk, bk, g_K, false);
}

// ------ 3xTF32 scores: E[rh][n][m] = exp(Q.K^T/4); Z[rh][n] += row sums ----
// (Round 7 shape: grid (16,16,32), 73.7KB smem, 2 CTA/SM; exp via MUFU)
__global__ void __launch_bounds__(256) k_scores() {
    extern __shared__ unsigned su[];
    unsigned* Qh = su;
    unsigned* Ql = su + 128 * GS;
    unsigned* Kh = su + 2 * 128 * GS;
    unsigned* Kl = su + 3 * 128 * GS;
    int tid = threadIdx.x;
    int wid = tid >> 5, lane = tid & 31;
    int gid = lane >> 2, tig = lane & 3;
    int warpM = wid >> 2, warpN = wid & 3;
    int mbase = blockIdx.x * 128, nbase = blockIdx.y * 128;
    int rh = blockIdx.z;
    int r = rh >> 3, h = rh & 7;
    const float* Qb = g_Q + (size_t)r * NNODE * DDIM + h * DH;
    const float* Kb = g_K + (size_t)r * NNODE * DDIM + h * DH;

    float c[4][4][4];
    #pragma unroll
    for (int mt = 0; mt < 4; mt++)
        #pragma unroll
        for (int nt = 0; nt < 4; nt++)
            #pragma unroll
            for (int j = 0; j < 4; j++) c[mt][nt][j] = 0.f;

    for (int kc = 0; kc < DH; kc += 32) {
        __syncthreads();
        #pragma unroll
        for (int l = 0; l < 4; l++) {
            int u = l * 256 + tid;
            int row = u >> 3, c4 = (u & 7) * 4;
            float4 v = *(const float4*)(Qb + (size_t)(nbase + row) * DDIM + kc + c4);
            unsigned h0, l0;
            tf32_split(v.x, h0, l0); Qh[row*GS + c4 + 0] = h0; Ql[row*GS + c4 + 0] = l0;
            tf32_split(v.y, h0, l0); Qh[row*GS + c4 + 1] = h0; Ql[row*GS + c4 + 1] = l0;
            tf32_split(v.z, h0, l0); Qh[row*GS + c4 + 2] = h0; Ql[row*GS + c4 + 2] = l0;
            tf32_split(v.w, h0, l0); Qh[row*GS + c4 + 3] = h0; Ql[row*GS + c4 + 3] = l0;
            float4 w = *(const float4*)(Kb + (size_t)(mbase + row) * DDIM + kc + c4);
            tf32_split(w.x, h0, l0); Kh[row*GS + c4 + 0] = h0; Kl[row*GS + c4 + 0] = l0;
            tf32_split(w.y, h0, l0); Kh[row*GS + c4 + 1] = h0; Kl[row*GS + c4 + 1] = l0;
            tf32_split(w.z, h0, l0); Kh[row*GS + c4 + 2] = h0; Kl[row*GS + c4 + 2] = l0;
            tf32_split(w.w, h0, l0); Kh[row*GS + c4 + 3] = h0; Kl[row*GS + c4 + 3] = l0;
        }
        __syncthreads();
        #pragma unroll
        for (int k8 = 0; k8 < 32; k8 += 8) {
            unsigned ah[4][4], al[4][4];
            #pragma unroll
            for (int mt = 0; mt < 4; mt++) {
                int r0 = (warpM * 64 + mt * 16 + gid) * GS + k8 + tig;
                ah[mt][0] = Qh[r0];             al[mt][0] = Ql[r0];
                ah[mt][1] = Qh[r0 + 8 * GS];    al[mt][1] = Ql[r0 + 8 * GS];
                ah[mt][2] = Qh[r0 + 4];         al[mt][2] = Ql[r0 + 4];
                ah[mt][3] = Qh[r0 + 8 * GS + 4];al[mt][3] = Ql[r0 + 8 * GS + 4];
            }
            #pragma unroll
            for (int nt = 0; nt < 4; nt++) {
                int q0 = (warpN * 32 + nt * 8 + gid) * GS + k8 + tig;
                unsigned bh[2], bl[2];
                bh[0] = Kh[q0]; bh[1] = Kh[q0 + 4];
                bl[0] = Kl[q0]; bl[1] = Kl[q0 + 4];
                #pragma unroll
                for (int mt = 0; mt < 4; mt++) {
                    mma_tf32(c[mt][nt], al[mt], bh);
                    mma_tf32(c[mt][nt], ah[mt], bl);
                    mma_tf32(c[mt][nt], ah[mt], bh);
                }
            }
        }
    }
    // E = exp(s) via MUFU (idle pipe); streaming store; row sums -> atomics
    #pragma unroll
    for (int mt = 0; mt < 4; mt++) {
        int ni = nbase + warpM * 64 + mt * 16 + gid;
        float* So = g_S + ((size_t)rh * NNODE + ni) * NNODE;
        float pl = 0.f, pu = 0.f;
        #pragma unroll
        for (int nt = 0; nt < 4; nt++) {
            int mj = mbase + warpN * 32 + nt * 8 + 2 * tig;
            float e00 = __expf(c[mt][nt][0] * 0.25f);
            float e01 = __expf(c[mt][nt][1] * 0.25f);
            float e10 = __expf(c[mt][nt][2] * 0.25f);
            float e11 = __expf(c[mt][nt][3] * 0.25f);
            float2 o0; o0.x = e00; o0.y = e01;
            float2 o1; o1.x = e10; o1.y = e11;
            __stcs((float2*)(So + mj), o0);
            __stcs((float2*)(So + (size_t)8 * NNODE + mj), o1);
            pl += e00 + e01;
            pu += e10 + e11;
        }
        pl += __shfl_xor_sync(~0u, pl, 1); pl += __shfl_xor_sync(~0u, pl, 2);
        pu += __shfl_xor_sync(~0u, pu, 1); pu += __shfl_xor_sync(~0u, pu, 2);
        if (tig == 0) {
            atomicAdd(&g_Z[rh * NNODE + ni],     pl);
            atomicAdd(&g_Z[rh * NNODE + ni + 8], pu);
        }
    }
}

// ---------------- selection: streaming A accumulation + exact top-3 --------
__global__ void __launch_bounds__(256) k_select(float* __restrict__ out) {
    __shared__ float sA[2048];
    __shared__ float sW[8];  __shared__ int sWi[8];
    __shared__ float topv[5]; __shared__ int topi[5];
    __shared__ int scount;
    int tid = threadIdx.x, lane = tid & 31, wid = tid >> 5;
    int b = blockIdx.x;
    int r = b >> 11, n = b & (NNODE - 1);
    const float* Sb = g_S + ((size_t)r * NHEAD * NNODE + n) * NNODE;

    float iz[NHEAD];
    #pragma unroll
    for (int h = 0; h < NHEAD; h++)
        iz[h] = 0.125f / g_Z[(r * NHEAD + h) * NNODE + n];

    float acc[8];
    #pragma unroll
    for (int l = 0; l < 8; l++) acc[l] = 0.f;

    #pragma unroll
    for (int h = 0; h < NHEAD; h++) {
        const float* row = Sb + (size_t)h * NNODE * NNODE;
        float4 v0 = __ldcs((const float4*)(row + 4 * tid));
        float4 v1 = __ldcs((const float4*)(row + 4 * (256 + tid)));
        float z = iz[h];
        acc[0] = fmaf(v0.x, z, acc[0]); acc[1] = fmaf(v0.y, z, acc[1]);
        acc[2] = fmaf(v0.z, z, acc[2]); acc[3] = fmaf(v0.w, z, acc[3]);
        acc[4] = fmaf(v1.x, z, acc[4]); acc[5] = fmaf(v1.y, z, acc[5]);
        acc[6] = fmaf(v1.z, z, acc[6]); acc[7] = fmaf(v1.w, z, acc[7]);
    }

    *(float4*)(sA + 4 * tid)         = make_float4(acc[0], acc[1], acc[2], acc[3]);
    *(float4*)(sA + 4 * (256 + tid)) = make_float4(acc[4], acc[5], acc[6], acc[7]);
    __syncthreads();

    for (int s = 0; s < 5; s++) {
        float bv = -2.f; int bi = 0;
        #pragma unroll
        for (int l = 0; l < 8; l++) {
            int m = l * 256 + tid;
            float v = sA[m];
            if (v > bv || (v == bv && m < bi)) { bv = v; bi = m; }
        }
        #pragma unroll
        for (int o = 16; o; o >>= 1) {
            float v2 = __shfl_xor_sync(~0u, bv, o);
            int   i2 = __shfl_xor_sync(~0u, bi, o);
            if (v2 > bv || (v2 == bv && i2 < bi)) { bv = v2; bi = i2; }
        }
        if (lane == 0) { sW[wid] = bv; sWi[wid] = bi; }
        __syncthreads();
        if (tid == 0) {
            float fv = sW[0]; int fi = sWi[0];
            #pragma unroll
            for (int w = 1; w < 8; w++) {
                if (sW[w] > fv || (sW[w] == fv && sWi[w] < fi)) { fv = sW[w]; fi = sWi[w]; }
            }
            topv[s] = fv; topi[s] = fi; sA[fi] = -1.f;
        }
        __syncthreads();
    }
    if (tid == 0) {
        #pragma unroll
        for (int s = 0; s < 5; s++) sA[topi[s]] = topv[s];
        scount = 0;
    }
    __syncthreads();

    float fifth = topv[4];
    int c = 0;
    #pragma unroll
    for (int l = 0; l < 8; l++) if (sA[l * 256 + tid] == fifth) c++;
    if (c) atomicAdd(&scount, c);
    __syncthreads();

    if (tid == 0) {
        int sel[3]; float val[3];
        int cnt = scount;
        if (cnt <= 3) {
            sel[0] = topi[0]; sel[1] = topi[1]; sel[2] = topi[2];
            val[0] = topv[0]; val[1] = topv[1]; val[2] = topv[2];
        } else {
            int mg = 0;
            while (mg < 5 && topv[mg] > fifth) mg++;
            int bd[3] = {1 << 29, 1 << 29, 1 << 29};
            int bs[3] = {0, 0, 0};
            #define CONSIDER(IDX) { int d_ = (IDX) >= n ? (IDX) - n : n - (IDX);            \
                if (d_ < bd[0]) { bd[2]=bd[1]; bs[2]=bs[1]; bd[1]=bd[0]; bs[1]=bs[0];       \
                                  bd[0]=d_; bs[0]=(IDX); }                                   \
                else if (d_ < bd[1]) { bd[2]=bd[1]; bs[2]=bs[1]; bd[1]=d_; bs[1]=(IDX); }    \
                else if (d_ < bd[2]) { bd[2]=d_; bs[2]=(IDX); } }
            for (int p = 0; p < mg; p++) CONSIDER(topi[p]);
            int taken = mg;
            for (int idx = 0; idx < NNODE && taken < cnt; idx++)
                if (sA[idx] == fifth) { CONSIDER(idx); taken++; }
            #undef CONSIDER
            sel[0] = bs[0]; sel[1] = bs[1]; sel[2] = bs[2];
            val[0] = sA[bs[0]]; val[1] = sA[bs[1]]; val[2] = sA[bs[2]];
        }
        size_t ebase = ((size_t)r * NNODE + n) * 3;
        #pragma unroll
        for (int k = 0; k < 3; k++) {
            size_t e = ebase + k;
            out[e * 3 + 0] = (float)n;
            out[e * 3 + 1] = (float)sel[k];
            out[e * 3 + 2] = (float)r;
            g_val[e] = val[k];
            atomicMin(&g_minBits, __float_as_uint(val[k]));
            atomicMax(&g_maxBits, __float_as_uint(val[k]));
        }
    }
}

// ---------------- final normalize ----------------
__global__ void k_norm(float* __restrict__ out) {
    int e = blockIdx.x * blockDim.x + threadIdx.x;
    if (e < NSEL) {
        float mn = __uint_as_float(g_minBits);
        float mx = __uint_as_float(g_maxBits);
        out[NSEL * 3 + e] = (g_val[e] - mn) / (mx - mn + EPSV);
    }
}

// ---------------- host launcher ----------------
extern "C" void kernel_launch(void* const* d_in, const int* in_sizes, int n_in,
                              void* d_out, int out_size) {
    const float* nf = (const float*)d_in[0];
    const int*   el = (const int*)  d_in[1];
    const float* ew = (const float*)d_in[2];
    const float* Wl = (const float*)d_in[3];
    const float* bl = (const float*)d_in[4];
    const float* Wq = (const float*)d_in[5];
    const float* bq = (const float*)d_in[6];
    const float* Wk = (const float*)d_in[7];
    const float* bk = (const float*)d_in[8];
    float* out = (float*)d_out;

    const int MMSM = 4 * 128 * GS * 4;   // 73728 bytes
    cudaFuncSetAttribute(k_gemm_feat, cudaFuncAttributeMaxDynamicSharedMemorySize, MMSM);
    cudaFuncSetAttribute(k_gemm_qk,   cudaFuncAttributeMaxDynamicSharedMemorySize, MMSM);
    cudaFuncSetAttribute(k_scores,    cudaFuncAttributeMaxDynamicSharedMemorySize, MMSM);

    k_zero<<<256, 256>>>();
    k_hist<<<E_EDGES / 256, 256>>>(el, ew);
    k_scan<<<1, 1024>>>();
    k_scatter<<<E_EDGES / 256, 256>>>(el);
    k_update<<<NSEG, 128>>>(el, ew, nf);
    k_gemm_feat<<<dim3(4, 64), 256, MMSM>>>(Wl, bl);
    k_gemm_qk  <<<dim3(4, 64, 2), 256, MMSM>>>(Wq, bq, Wk, bk);
    k_scores<<<dim3(16, 16, NRH), 256, MMSM>>>();
    k_select<<<NSEG, 256>>>(out);
    k_norm<<<NSEL / 256, 256>>>(out);
}